// round 5
// baseline (speedup 1.0000x reference)
#include <cuda_runtime.h>
#include <cuda_bf16.h>

// Problem constants: B=16, N=1024, M=4096, D=64
#define BB 16
#define NN 1024
#define MM 4096
#define DD 64
#define INF_BITS 0x7f800000u

// ---------------- device scratch (no cudaMalloc allowed) ----------------
__device__ float g_C[(size_t)BB * NN * MM];                 // 256 MB cost matrix
__device__ float g_x2[BB * NN];
__device__ float g_y2[BB * MM];
// packed moves: 4 cells per byte (2 bits each), row stride = MM/4 = 1024 bytes.
// +128 pad: backtrack tile loads may read up to ~80B past the last row end.
__device__ unsigned char g_mv[(size_t)BB * NN * (MM / 4) + 128];
// inter-CTA boundary handoff: one word per row per interface (3 per batch).
__device__ unsigned g_bnd[BB][3][NN];
// per-CTA last-row argmin partials
__device__ float g_pv[BB][4];
__device__ int g_pi[BB][4];

__device__ __forceinline__ unsigned ldcg_u32(const unsigned* p) {
    unsigned v;
    asm volatile("ld.global.cg.u32 %0, [%1];" : "=r"(v) : "l"(p));
    return v;
}
__device__ __forceinline__ void stcg_u32(unsigned* p, unsigned v) {
    asm volatile("st.global.cg.u32 [%0], %1;" :: "l"(p), "r"(v));
}

// ---------------- kernel 0a: row squared norms ----------------
__global__ void norms_kernel(const float* __restrict__ x, const float* __restrict__ y) {
    int idx = blockIdx.x * blockDim.x + threadIdx.x;
    const float* src;
    float* dst;
    if (idx < BB * NN) {
        src = x + (size_t)idx * DD;
        dst = g_x2 + idx;
    } else if (idx < BB * NN + BB * MM) {
        int k = idx - BB * NN;
        src = y + (size_t)k * DD;
        dst = g_y2 + k;
    } else {
        return;
    }
    float s = 0.f;
#pragma unroll
    for (int q = 0; q < DD / 4; q++) {
        float4 v = *(const float4*)(src + q * 4);
        s += v.x * v.x + v.y * v.y + v.z * v.z + v.w * v.w;
    }
    *dst = s;
}

// ---------------- kernel 0b: reset boundary sentinels ----------------
__global__ void init_bnd_kernel() {
    int i = blockIdx.x * blockDim.x + threadIdx.x;
    if (i < BB * 3 * NN) ((unsigned*)g_bnd)[i] = INF_BITS;
}

// ---------------- kernel 1: C = x2 + y2 - 2 * x @ y^T ----------------
// 128x128 tile, 256 threads, 8x8 micro-tile, BK=32 (2 k-steps of D=64).
__global__ void __launch_bounds__(256) gemm_kernel(const float* __restrict__ x,
                                                   const float* __restrict__ y) {
    __shared__ float Xs[32][128];
    __shared__ float Ys[32][128];
    int b = blockIdx.z;
    int i0 = blockIdx.y * 128;
    int j0 = blockIdx.x * 128;
    const float* xb = x + (size_t)b * NN * DD;
    const float* yb = y + (size_t)b * MM * DD;
    int tid = threadIdx.x;
    int txc = tid & 15, tyc = tid >> 4;

    float acc[8][8];
#pragma unroll
    for (int a = 0; a < 8; a++)
#pragma unroll
        for (int c = 0; c < 8; c++) acc[a][c] = 0.f;

#pragma unroll
    for (int kt = 0; kt < DD; kt += 32) {
#pragma unroll
        for (int p = 0; p < 4; p++) {
            int idx = tid + p * 256;     // 0..1023
            int q = idx & 7;             // which float4 in the 32-wide k slab
            int r = idx >> 3;            // tile row 0..127
            float4 xv = *(const float4*)(xb + (size_t)(i0 + r) * DD + kt + q * 4);
            Xs[q * 4 + 0][r] = xv.x;
            Xs[q * 4 + 1][r] = xv.y;
            Xs[q * 4 + 2][r] = xv.z;
            Xs[q * 4 + 3][r] = xv.w;
            float4 yv = *(const float4*)(yb + (size_t)(j0 + r) * DD + kt + q * 4);
            Ys[q * 4 + 0][r] = yv.x;
            Ys[q * 4 + 1][r] = yv.y;
            Ys[q * 4 + 2][r] = yv.z;
            Ys[q * 4 + 3][r] = yv.w;
        }
        __syncthreads();
#pragma unroll
        for (int kk = 0; kk < 32; kk++) {
            float xf[8], yf[8];
            *(float4*)&xf[0] = *(const float4*)&Xs[kk][tyc * 4];
            *(float4*)&xf[4] = *(const float4*)&Xs[kk][64 + tyc * 4];
            *(float4*)&yf[0] = *(const float4*)&Ys[kk][txc * 4];
            *(float4*)&yf[4] = *(const float4*)&Ys[kk][64 + txc * 4];
#pragma unroll
            for (int mm = 0; mm < 8; mm++)
#pragma unroll
                for (int nn = 0; nn < 8; nn++)
                    acc[mm][nn] = fmaf(xf[mm], yf[nn], acc[mm][nn]);
        }
        __syncthreads();
    }

    float y2v[8];
    *(float4*)&y2v[0] = *(const float4*)(g_y2 + b * MM + j0 + txc * 4);
    *(float4*)&y2v[4] = *(const float4*)(g_y2 + b * MM + j0 + 64 + txc * 4);
#pragma unroll
    for (int mm = 0; mm < 8; mm++) {
        int row = i0 + ((mm < 4) ? (tyc * 4 + mm) : (64 + tyc * 4 + mm - 4));
        float x2v = g_x2[b * NN + row];
        float* crow = g_C + ((size_t)b * NN + row) * MM + j0;
        float4 v0, v1;
        v0.x = x2v + y2v[0] - 2.f * acc[mm][0];
        v0.y = x2v + y2v[1] - 2.f * acc[mm][1];
        v0.z = x2v + y2v[2] - 2.f * acc[mm][2];
        v0.w = x2v + y2v[3] - 2.f * acc[mm][3];
        v1.x = x2v + y2v[4] - 2.f * acc[mm][4];
        v1.y = x2v + y2v[5] - 2.f * acc[mm][5];
        v1.z = x2v + y2v[6] - 2.f * acc[mm][6];
        v1.w = x2v + y2v[7] - 2.f * acc[mm][7];
        *(float4*)(crow + txc * 4) = v0;
        *(float4*)(crow + 64 + txc * 4) = v1;
    }
}

// ---------------- kernel 2: systolic subsequence-DTW forward DP ----------------
// 4 CTAs x 8 warps per batch. Warp owns a 128-col slice (4 cols/lane) kept in
// registers. Row recurrence D[j] = min(a[j], D[j-1] + C[j]) via min-plus pair
// scan (S, M); the left boundary B enters as a carry applied AFTER the scan:
//   prefix-with-carry M' = min(B + Sprefix, Mprefix)
// so the scan runs speculatively and the cross-warp critical path is ~2 flops.
// Boundaries: intra-CTA via an 8-deep smem ring (word value doubles as flag,
// INF sentinel, consumer resets); inter-CTA via g_bnd (one word per row).
__device__ __forceinline__ unsigned mvcode(float dd, float du, float dl) {
    // priority: diagonal, up, left — matches the reference backtrack
    unsigned m = (du <= dl) ? 1u : 2u;
    if (dd <= du && dd <= dl) m = 0u;
    return m;
}

__global__ void __launch_bounds__(256) dtw_kernel() {
    const unsigned FULL = 0xffffffffu;
    const float INF = __uint_as_float(INF_BITS);
    int cta = blockIdx.x;
    int b = cta >> 2, r = cta & 3;
    int t = threadIdx.x, lane = t & 31, w = t >> 5;   // w in 0..7

    const float* Cp = g_C + (size_t)b * NN * MM + r * 1024 + w * 128 + lane * 4;
    unsigned char* mvp = g_mv + (size_t)b * NN * (MM / 4) + r * 256 + w * 32 + lane;

    __shared__ volatile unsigned sB[7][8];   // ring: interface w -> w+1
    __shared__ float sRv[8];
    __shared__ int sRi[8];
    if (t < 56) sB[t >> 3][t & 7] = INF_BITS;
    __syncthreads();

    const bool leftEdge = (w == 0 && r == 0);
    const bool hasGin = (w == 0 && r > 0);
    const bool hasGout = (w == 7 && r < 3);
    const unsigned* gin = hasGin ? &g_bnd[b][r - 1][0] : (const unsigned*)0;
    unsigned* gout = hasGout ? &g_bnd[b][r][0] : (unsigned*)0;

    // ---- row 0: D = C[0,:] ----
    float4 c4 = *(const float4*)Cp;
    float pd0 = c4.x, pd1 = c4.y, pd2 = c4.z, pd3 = c4.w;

    // publish row-0 boundary (D[0][chunk_end])
    float bO = __shfl_sync(FULL, pd3, 31);
    if (lane == 0) {
        unsigned vb = __float_as_uint(bO);
        if (w < 7) sB[w][0] = vb;
        else if (hasGout) stcg_u32(gout + 0, vb);
    }

    // pLeft = D[0][4t-1]; lane0 consumes the left neighbor's row-0 boundary
    float pLeft = __shfl_up_sync(FULL, pd3, 1);
    {
        unsigned vb = INF_BITS;
        if (lane == 0) {
            if (w > 0) {
                volatile unsigned* sl = &sB[w - 1][0];
                do { vb = *sl; } while (vb == INF_BITS);
                *sl = INF_BITS;
            } else if (hasGin) {
                do { vb = ldcg_u32(gin + 0); } while (vb == INF_BITS);
            }
            pLeft = __uint_as_float(vb);    // INF for left edge
        }
    }

    float4 cur = *(const float4*)(Cp + MM);
    float4 nxt = *(const float4*)(Cp + 2 * (size_t)MM);
    unsigned pfB = INF_BITS;
    if (hasGin && lane == 0) pfB = ldcg_u32(gin + 1);

    for (int i = 1; i < NN; i++) {
        // prefetch C row i+2 and inter-CTA boundary for row i+1
        float4 pf = cur;
        if (i + 2 < NN) pf = *(const float4*)(Cp + (size_t)(i + 2) * MM);
        unsigned pfBn = INF_BITS;
        if (hasGin && lane == 0 && i + 1 < NN) pfBn = ldcg_u32(gin + i + 1);

        float c0 = cur.x, c1 = cur.y, c2 = cur.z, c3 = cur.w;
        float a0 = fminf(pd0, pLeft) + c0;
        float a1 = fminf(pd1, pd0) + c1;
        float a2 = fminf(pd2, pd1) + c2;
        float a3 = fminf(pd3, pd2) + c3;

        // thread-local compose of 4 elements
        float Sl = c0, Ml = a0;
        Sl += c1; Ml = fminf(Ml + c1, a1);
        Sl += c2; Ml = fminf(Ml + c2, a2);
        Sl += c3; Ml = fminf(Ml + c3, a3);

        // warp inclusive min-plus pair scan (speculative w.r.t. boundary B)
        float iS = Sl, iM = Ml;
#pragma unroll
        for (int off = 1; off < 32; off <<= 1) {
            float oS = __shfl_up_sync(FULL, iS, off);
            float oM = __shfl_up_sync(FULL, iM, off);
            if (lane >= off) { iM = fminf(oM + iS, iM); iS = oS + iS; }
        }
        float eS = __shfl_up_sync(FULL, iS, 1);
        float eM = __shfl_up_sync(FULL, iM, 1);
        if (lane == 0) { eS = 0.f; eM = INF; }
        float Stot = __shfl_sync(FULL, iS, 31);
        float Mtot = __shfl_sync(FULL, iM, 31);

        // acquire left boundary B = D[i][chunk_start-1]
        unsigned vb = INF_BITS;
        if (lane == 0) {
            if (w > 0) {
                volatile unsigned* sl = &sB[w - 1][i & 7];
                do { vb = *sl; } while (vb == INF_BITS);
                *sl = INF_BITS;
            } else if (hasGin) {
                vb = pfB;
                while (vb == INF_BITS) vb = ldcg_u32(gin + i);
            }
        }
        vb = __shfl_sync(FULL, vb, 0);
        float B = __uint_as_float(vb);

        // publish own boundary ASAP: D[i][chunk_end] = min(B + Stot, Mtot)
        float BoutV = fminf(B + Stot, Mtot);
        if (lane == 0) {
            unsigned ob = __float_as_uint(BoutV);
            if (w < 7) {
                volatile unsigned* sl = &sB[w][i & 7];
                while (*sl != INF_BITS) {}   // back-pressure (ring depth 8)
                *sl = ob;
            } else if (hasGout) {
                stcg_u32(gout + i, ob);
            }
        }

        // finalize this thread's 4 D values with the carry applied
        float M_ex = fminf(B + eS, eM);      // == D[i][4t-1]
        float Mr = M_ex;
        Mr = fminf(Mr + c0, a0); float nd0 = Mr;
        Mr = fminf(Mr + c1, a1); float nd1 = Mr;
        Mr = fminf(Mr + c2, a2); float nd2 = Mr;
        Mr = fminf(Mr + c3, a3); float nd3 = Mr;

        // move codes (dd = Dprev[j-1], du = Dprev[j], dl = D[i][j-1])
        unsigned m0 = mvcode(pLeft, pd0, M_ex);
        unsigned m1 = mvcode(pd0, pd1, nd0);
        unsigned m2 = mvcode(pd1, pd2, nd1);
        unsigned m3 = mvcode(pd2, pd3, nd2);
        mvp[(size_t)i * (MM / 4)] =
            (unsigned char)(m0 | (m1 << 2) | (m2 << 4) | (m3 << 6));

        pLeft = M_ex;
        pd0 = nd0; pd1 = nd1; pd2 = nd2; pd3 = nd3;
        cur = nxt; nxt = pf; pfB = pfBn;
    }

    // ---- per-CTA argmin of last row (first index on exact ties) ----
    int base = r * 1024 + w * 128 + lane * 4;
    float bv = pd0; int bi = base;
    if (pd1 < bv) { bv = pd1; bi = base + 1; }
    if (pd2 < bv) { bv = pd2; bi = base + 2; }
    if (pd3 < bv) { bv = pd3; bi = base + 3; }
#pragma unroll
    for (int off = 16; off > 0; off >>= 1) {
        float ov = __shfl_down_sync(FULL, bv, off);
        int oi = __shfl_down_sync(FULL, bi, off);
        if (ov < bv || (ov == bv && oi < bi)) { bv = ov; bi = oi; }
    }
    if (lane == 0) { sRv[w] = bv; sRi[w] = bi; }
    __syncthreads();
    if (t == 0) {
        float v = sRv[0]; int ix = sRi[0];
#pragma unroll
        for (int q = 1; q < 8; q++)
            if (sRv[q] < v || (sRv[q] == v && sRi[q] < ix)) { v = sRv[q]; ix = sRi[q]; }
        g_pv[b][r] = v;
        g_pi[b][r] = ix;
    }
}

// ---------------- kernel 3: backtrack over packed moves ----------------
// One warp per batch. 64-row x 20-word smem tile; lane0 walks it consuming a
// full 32-bit word (16 cells) at a time so left-runs cost ~1 LDS per 16 steps.
__global__ void __launch_bounds__(32) backtrack_kernel(const float* __restrict__ xt,
                                                       const float* __restrict__ yt,
                                                       float* __restrict__ out) {
    int b = blockIdx.x;
    int lane = threadIdx.x;
    __shared__ uint4 tile4[64][5];    // 64 rows x 80 bytes (20 words)
    __shared__ int syl[NN];
    __shared__ int sij[2];
    const unsigned* tw = (const unsigned*)tile4;
    const unsigned char* mvb = g_mv + (size_t)b * NN * (MM / 4);

    // final argmin across the 4 CTA partials (first global index on ties)
    if (lane == 0) {
        float bv = g_pv[b][0]; int bi = g_pi[b][0];
#pragma unroll
        for (int q = 1; q < 4; q++) {
            float v = g_pv[b][q]; int ix = g_pi[b][q];
            if (v < bv || (v == bv && ix < bi)) { bv = v; bi = ix; }
        }
        out[b] = bv;                  // dtw_cost
        syl[NN - 1] = bi;
        sij[0] = NN - 1; sij[1] = bi;
    }
    __syncwarp();
    int i = sij[0], j = sij[1];

    while (i > 0) {
        int r0 = i - 63; if (r0 < 1) r0 = 1;
        int wb0 = (j >> 4) - 15; if (wb0 < 0) wb0 = 0;
        wb0 &= ~3;                    // 16B-align the word window
        // cooperative tile load: rows r0..r0+63, words wb0..wb0+19
#pragma unroll
        for (int p = 0; p < 10; p++) {
            int idx = lane + p * 32;  // 0..319
            int rr = idx / 5, q = idx - rr * 5;
            tile4[rr][q] = *(const uint4*)(mvb + (size_t)(r0 + rr) * (MM / 4) + wb0 * 4 + q * 16);
        }
        __syncwarp();
        if (lane == 0) {
            while (i > 0 && i >= r0) {
                int wcol = (j >> 4) - wb0;
                if (wcol < 0) break;
                unsigned word = tw[(i - r0) * 20 + wcol];
                for (;;) {
                    unsigned mv = (word >> ((j & 15) * 2)) & 3u;
                    if (mv == 2u) {           // left
                        j--;
                        if ((j & 15) == 15) break;   // crossed word boundary
                    } else {                  // diag or up
                        i--;
                        j -= (mv == 0u);
                        syl[i] = j;
                        break;
                    }
                }
            }
            sij[0] = i; sij[1] = j;
        }
        __syncwarp();
        i = sij[0]; j = sij[1];
        __syncwarp();
    }

    // write w_ts (= x_t) and w_vs (= y_t gathered at per-row path column)
    for (int n = lane; n < NN; n += 32) {
        out[BB + b * NN + n] = xt[b * NN + n];
        out[BB + BB * NN + b * NN + n] = yt[(size_t)b * MM + syl[n]];
    }
}

// ---------------- launch ----------------
extern "C" void kernel_launch(void* const* d_in, const int* in_sizes, int n_in,
                              void* d_out, int out_size) {
    const float* x = (const float*)d_in[0];   // [16,1024,64]
    const float* y = (const float*)d_in[1];   // [16,4096,64]
    const float* xt = (const float*)d_in[2];  // [16,1024]
    const float* yt = (const float*)d_in[3];  // [16,4096]
    float* out = (float*)d_out;               // [16] cost, [16,1024] w_ts, [16,1024] w_vs

    int totalRows = BB * NN + BB * MM;
    norms_kernel<<<(totalRows + 255) / 256, 256>>>(x, y);

    init_bnd_kernel<<<(BB * 3 * NN + 255) / 256, 256>>>();

    dim3 gg(MM / 128, NN / 128, BB);
    gemm_kernel<<<gg, 256>>>(x, y);

    dtw_kernel<<<BB * 4, 256>>>();

    backtrack_kernel<<<BB, 32>>>(xt, yt, out);
}

// round 6
// speedup vs baseline: 2.9051x; 2.9051x over previous
#include <cuda_runtime.h>
#include <cuda_bf16.h>

// Problem constants: B=16, N=1024, M=4096, D=64
#define BB 16
#define NN 1024
#define MM 4096
#define DD 64
#define INF_BITS 0x7f800000u

// ---------------- device scratch (no cudaMalloc allowed) ----------------
__device__ float g_C[(size_t)BB * NN * MM];                 // 256 MB cost matrix
__device__ float g_x2[BB * NN];
__device__ float g_y2[BB * MM];
// packed moves: 4 cells per byte (2 bits each), row stride = MM/4 = 1024 bytes.
__device__ unsigned char g_mv[(size_t)BB * NN * (MM / 4) + 128];
// inter-CTA boundary handoff: one word per row (single interface per batch)
__device__ unsigned g_bnd[BB][NN];
// per-CTA last-row argmin partials (2 CTAs per batch)
__device__ float g_pv[BB][2];
__device__ int g_pi[BB][2];

__device__ __forceinline__ unsigned ldcg_u32(const unsigned* p) {
    unsigned v;
    asm volatile("ld.global.cg.u32 %0, [%1];" : "=r"(v) : "l"(p));
    return v;
}
__device__ __forceinline__ void stcg_u32(unsigned* p, unsigned v) {
    asm volatile("st.global.cg.u32 [%0], %1;" :: "l"(p), "r"(v));
}

// ---------------- kernel 0a: row squared norms ----------------
__global__ void norms_kernel(const float* __restrict__ x, const float* __restrict__ y) {
    int idx = blockIdx.x * blockDim.x + threadIdx.x;
    const float* src;
    float* dst;
    if (idx < BB * NN) {
        src = x + (size_t)idx * DD;
        dst = g_x2 + idx;
    } else if (idx < BB * NN + BB * MM) {
        int k = idx - BB * NN;
        src = y + (size_t)k * DD;
        dst = g_y2 + k;
    } else {
        return;
    }
    float s = 0.f;
#pragma unroll
    for (int q = 0; q < DD / 4; q++) {
        float4 v = *(const float4*)(src + q * 4);
        s += v.x * v.x + v.y * v.y + v.z * v.z + v.w * v.w;
    }
    *dst = s;
}

// ---------------- kernel 0b: reset boundary sentinels ----------------
__global__ void init_bnd_kernel() {
    int i = blockIdx.x * blockDim.x + threadIdx.x;
    if (i < BB * NN) ((unsigned*)g_bnd)[i] = INF_BITS;
}

// ---------------- kernel 1: C = x2 + y2 - 2 * x @ y^T ----------------
__global__ void __launch_bounds__(256) gemm_kernel(const float* __restrict__ x,
                                                   const float* __restrict__ y) {
    __shared__ float Xs[32][128];
    __shared__ float Ys[32][128];
    int b = blockIdx.z;
    int i0 = blockIdx.y * 128;
    int j0 = blockIdx.x * 128;
    const float* xb = x + (size_t)b * NN * DD;
    const float* yb = y + (size_t)b * MM * DD;
    int tid = threadIdx.x;
    int txc = tid & 15, tyc = tid >> 4;

    float acc[8][8];
#pragma unroll
    for (int a = 0; a < 8; a++)
#pragma unroll
        for (int c = 0; c < 8; c++) acc[a][c] = 0.f;

#pragma unroll
    for (int kt = 0; kt < DD; kt += 32) {
#pragma unroll
        for (int p = 0; p < 4; p++) {
            int idx = tid + p * 256;
            int q = idx & 7;
            int r = idx >> 3;
            float4 xv = *(const float4*)(xb + (size_t)(i0 + r) * DD + kt + q * 4);
            Xs[q * 4 + 0][r] = xv.x;
            Xs[q * 4 + 1][r] = xv.y;
            Xs[q * 4 + 2][r] = xv.z;
            Xs[q * 4 + 3][r] = xv.w;
            float4 yv = *(const float4*)(yb + (size_t)(j0 + r) * DD + kt + q * 4);
            Ys[q * 4 + 0][r] = yv.x;
            Ys[q * 4 + 1][r] = yv.y;
            Ys[q * 4 + 2][r] = yv.z;
            Ys[q * 4 + 3][r] = yv.w;
        }
        __syncthreads();
#pragma unroll
        for (int kk = 0; kk < 32; kk++) {
            float xf[8], yf[8];
            *(float4*)&xf[0] = *(const float4*)&Xs[kk][tyc * 4];
            *(float4*)&xf[4] = *(const float4*)&Xs[kk][64 + tyc * 4];
            *(float4*)&yf[0] = *(const float4*)&Ys[kk][txc * 4];
            *(float4*)&yf[4] = *(const float4*)&Ys[kk][64 + txc * 4];
#pragma unroll
            for (int mm = 0; mm < 8; mm++)
#pragma unroll
                for (int nn = 0; nn < 8; nn++)
                    acc[mm][nn] = fmaf(xf[mm], yf[nn], acc[mm][nn]);
        }
        __syncthreads();
    }

    float y2v[8];
    *(float4*)&y2v[0] = *(const float4*)(g_y2 + b * MM + j0 + txc * 4);
    *(float4*)&y2v[4] = *(const float4*)(g_y2 + b * MM + j0 + 64 + txc * 4);
#pragma unroll
    for (int mm = 0; mm < 8; mm++) {
        int row = i0 + ((mm < 4) ? (tyc * 4 + mm) : (64 + tyc * 4 + mm - 4));
        float x2v = g_x2[b * NN + row];
        float* crow = g_C + ((size_t)b * NN + row) * MM + j0;
        float4 v0, v1;
        v0.x = x2v + y2v[0] - 2.f * acc[mm][0];
        v0.y = x2v + y2v[1] - 2.f * acc[mm][1];
        v0.z = x2v + y2v[2] - 2.f * acc[mm][2];
        v0.w = x2v + y2v[3] - 2.f * acc[mm][3];
        v1.x = x2v + y2v[4] - 2.f * acc[mm][4];
        v1.y = x2v + y2v[5] - 2.f * acc[mm][5];
        v1.z = x2v + y2v[6] - 2.f * acc[mm][6];
        v1.w = x2v + y2v[7] - 2.f * acc[mm][7];
        *(float4*)(crow + txc * 4) = v0;
        *(float4*)(crow + 64 + txc * 4) = v1;
    }
}

// ---------------- kernel 2: wavefront subsequence-DTW forward DP ----------------
// 2 CTAs per batch, 8 warps/CTA, warp owns 256 cols (8 per lane, in regs).
// Skewed pipeline: at step s, warp w processes row i = s - w. One
// __syncthreads per step clocks the wave; the left-neighbor boundary
// D[i][chunk_start-1] moves through a double-buffered smem slot written the
// previous step. NO intra-CTA spinning. The single inter-CTA interface per
// batch uses a gmem word per row (INF sentinel, 1-row prefetch); the consumer
// CTA runs ~8 rows behind and does not spin in steady state.
__global__ void __launch_bounds__(256, 1) dtw_kernel() {
    const unsigned FULL = 0xffffffffu;
    const float INF = __uint_as_float(INF_BITS);
    int cta = blockIdx.x;
    int b = cta >> 1, r = cta & 1;                 // r: half index (0 left, 1 right)
    int t = threadIdx.x, lane = t & 31, w = t >> 5;
    int colbase = r * (MM / 2) + w * 256 + lane * 8;
    const float* Cp = g_C + (size_t)b * NN * MM + colbase;
    unsigned short* mvp =
        (unsigned short*)(g_mv + (size_t)b * NN * (MM / 4) + (colbase >> 2));

    __shared__ float sBnd[2][9];                   // double-buffered boundary slots
    __shared__ float sRv[8];
    __shared__ int sRi[8];

    const bool gin = (r == 1 && w == 0);           // consumes gmem boundary
    const bool gout = (r == 0 && w == 7);          // produces gmem boundary
    unsigned* gb = &g_bnd[b][0];

    float pd[8], n1[8], n2[8];
    // preload rows 0 and 1 of this warp's chunk
    *(float4*)&n1[0] = *(const float4*)(Cp);
    *(float4*)&n1[4] = *(const float4*)(Cp + 4);
    *(float4*)&n2[0] = *(const float4*)(Cp + MM);
    *(float4*)&n2[4] = *(const float4*)(Cp + MM + 4);

    float prevB = INF;          // D[i-1][chunk_start-1] (lane0's diagonal input)
    unsigned pfB = INF_BITS;    // gmem boundary prefetch register
    __syncthreads();

    for (int s = 0; s < NN + 7; s++) {
        int i = s - w;
        int buf = s & 1;
        if (i >= 0 && i < NN) {
            float c[8];
#pragma unroll
            for (int k = 0; k < 8; k++) c[k] = n1[k];
#pragma unroll
            for (int k = 0; k < 8; k++) n1[k] = n2[k];
            if (i + 2 < NN) {
                *(float4*)&n2[0] = *(const float4*)(Cp + (size_t)(i + 2) * MM);
                *(float4*)&n2[4] = *(const float4*)(Cp + (size_t)(i + 2) * MM + 4);
            }

            if (i == 0) {
                // row 0: D = C[0,:]
#pragma unroll
                for (int k = 0; k < 8; k++) pd[k] = c[k];
                // consume left boundary of row 0 (becomes prevB for row 1)
                float B = INF;
                unsigned vb = INF_BITS;
                if (w > 0) {
                    B = sBnd[buf][w];
                } else if (gin) {
                    if (lane == 0) {
                        do { vb = ldcg_u32(gb + 0); } while (vb == INF_BITS);
                        pfB = ldcg_u32(gb + 1);
                    }
                    vb = __shfl_sync(FULL, vb, 0);
                    B = __uint_as_float(vb);
                }
                prevB = B;
                // publish D[0][chunk_end]
                float dend = __shfl_sync(FULL, pd[7], 31);
                if (lane == 0) {
                    if (w < 7) sBnd[buf ^ 1][w + 1] = dend;
                    else if (gout) stcg_u32(gb + 0, __float_as_uint(dend));
                }
            } else {
                // pl_k = D[i-1][j-1]
                float pl0 = __shfl_up_sync(FULL, pd[7], 1);
                if (lane == 0) pl0 = prevB;
                float a[8];
                a[0] = fminf(pd[0], pl0) + c[0];
#pragma unroll
                for (int k = 1; k < 8; k++) a[k] = fminf(pd[k], pd[k - 1]) + c[k];
                // thread-local min-plus compose of 8 elements
                float Sl = c[0], Ml = a[0];
#pragma unroll
                for (int k = 1; k < 8; k++) {
                    Sl += c[k];
                    Ml = fminf(Ml + c[k], a[k]);
                }
                // warp inclusive min-plus pair scan (speculative w.r.t. B)
                float iS = Sl, iM = Ml;
#pragma unroll
                for (int off = 1; off < 32; off <<= 1) {
                    float oS = __shfl_up_sync(FULL, iS, off);
                    float oM = __shfl_up_sync(FULL, iM, off);
                    if (lane >= off) { iM = fminf(oM + iS, iM); iS = oS + iS; }
                }
                float eS = __shfl_up_sync(FULL, iS, 1);
                float eM = __shfl_up_sync(FULL, iM, 1);
                if (lane == 0) { eS = 0.f; eM = INF; }

                // acquire left boundary B = D[i][chunk_start-1]
                float B = INF;
                unsigned vb = INF_BITS;
                if (w > 0) {
                    B = sBnd[buf][w];
                } else if (gin) {
                    if (lane == 0) {
                        vb = pfB;
                        while (vb == INF_BITS) vb = ldcg_u32(gb + i);
                        if (i + 1 < NN) pfB = ldcg_u32(gb + i + 1);
                    }
                    vb = __shfl_sync(FULL, vb, 0);
                    B = __uint_as_float(vb);
                }

                // publish own boundary ASAP (lane 31 holds the chunk totals)
                if (lane == 31) {
                    float dend = fminf(B + iS, iM);
                    if (w < 7) sBnd[buf ^ 1][w + 1] = dend;
                    else if (gout) stcg_u32(gb + i, __float_as_uint(dend));
                }

                // finalize with carry applied
                float M_ex = fminf(B + eS, eM);    // == D[i][lane_start-1]
                float nd[8];
                float Mr = M_ex;
#pragma unroll
                for (int k = 0; k < 8; k++) {
                    Mr = fminf(Mr + c[k], a[k]);
                    nd[k] = Mr;
                }
                // move codes (dd = D[i-1][j-1], du = D[i-1][j], dl = D[i][j-1])
                unsigned pk = 0;
                float dl = M_ex, dd = pl0;
#pragma unroll
                for (int k = 0; k < 8; k++) {
                    float du = pd[k];
                    unsigned m = (du <= dl) ? 1u : 2u;
                    if (dd <= du && dd <= dl) m = 0u;
                    pk |= m << (2 * k);
                    dd = du;
                    dl = nd[k];
                }
                mvp[(size_t)i * (MM / 8)] = (unsigned short)pk;

                prevB = B;
#pragma unroll
                for (int k = 0; k < 8; k++) pd[k] = nd[k];
            }
        }
        __syncthreads();
    }

    // ---- per-CTA argmin of last row (first index on exact ties) ----
    float bv = pd[0];
    int bi = colbase;
#pragma unroll
    for (int k = 1; k < 8; k++)
        if (pd[k] < bv) { bv = pd[k]; bi = colbase + k; }
#pragma unroll
    for (int off = 16; off > 0; off >>= 1) {
        float ov = __shfl_down_sync(FULL, bv, off);
        int oi = __shfl_down_sync(FULL, bi, off);
        if (ov < bv || (ov == bv && oi < bi)) { bv = ov; bi = oi; }
    }
    if (lane == 0) { sRv[w] = bv; sRi[w] = bi; }
    __syncthreads();
    if (t == 0) {
        float v = sRv[0]; int ix = sRi[0];
#pragma unroll
        for (int q = 1; q < 8; q++)
            if (sRv[q] < v || (sRv[q] == v && sRi[q] < ix)) { v = sRv[q]; ix = sRi[q]; }
        g_pv[b][r] = v;
        g_pi[b][r] = ix;
    }
}

// ---------------- kernel 3: backtrack over packed moves ----------------
// One warp per batch. 64-row x 20-word smem tile; lane0 walks it consuming a
// full 32-bit word (16 cells) at a time so left-runs cost ~1 LDS per 16 steps.
__global__ void __launch_bounds__(32) backtrack_kernel(const float* __restrict__ xt,
                                                       const float* __restrict__ yt,
                                                       float* __restrict__ out) {
    int b = blockIdx.x;
    int lane = threadIdx.x;
    __shared__ uint4 tile4[64][5];    // 64 rows x 80 bytes (20 words)
    __shared__ int syl[NN];
    __shared__ int sij[2];
    const unsigned* tw = (const unsigned*)tile4;
    const unsigned char* mvb = g_mv + (size_t)b * NN * (MM / 4);

    // final argmin across the 2 CTA partials (first global index on ties)
    if (lane == 0) {
        float bv = g_pv[b][0]; int bi = g_pi[b][0];
        float v = g_pv[b][1]; int ix = g_pi[b][1];
        if (v < bv || (v == bv && ix < bi)) { bv = v; bi = ix; }
        out[b] = bv;                  // dtw_cost
        syl[NN - 1] = bi;
        sij[0] = NN - 1; sij[1] = bi;
    }
    __syncwarp();
    int i = sij[0], j = sij[1];

    while (i > 0) {
        int r0 = i - 63; if (r0 < 1) r0 = 1;
        int wb0 = (j >> 4) - 15; if (wb0 < 0) wb0 = 0;
        wb0 &= ~3;                    // 16B-align the word window
#pragma unroll
        for (int p = 0; p < 10; p++) {
            int idx = lane + p * 32;  // 0..319
            int rr = idx / 5, q = idx - rr * 5;
            tile4[rr][q] = *(const uint4*)(mvb + (size_t)(r0 + rr) * (MM / 4) + wb0 * 4 + q * 16);
        }
        __syncwarp();
        if (lane == 0) {
            while (i > 0 && i >= r0) {
                int wcol = (j >> 4) - wb0;
                if (wcol < 0) break;
                unsigned word = tw[(i - r0) * 20 + wcol];
                for (;;) {
                    unsigned mv = (word >> ((j & 15) * 2)) & 3u;
                    if (mv == 2u) {           // left
                        j--;
                        if ((j & 15) == 15) break;   // crossed word boundary
                    } else {                  // diag or up
                        i--;
                        j -= (mv == 0u);
                        syl[i] = j;
                        break;
                    }
                }
            }
            sij[0] = i; sij[1] = j;
        }
        __syncwarp();
        i = sij[0]; j = sij[1];
        __syncwarp();
    }

    // write w_ts (= x_t) and w_vs (= y_t gathered at per-row path column)
    for (int n = lane; n < NN; n += 32) {
        out[BB + b * NN + n] = xt[b * NN + n];
        out[BB + BB * NN + b * NN + n] = yt[(size_t)b * MM + syl[n]];
    }
}

// ---------------- launch ----------------
extern "C" void kernel_launch(void* const* d_in, const int* in_sizes, int n_in,
                              void* d_out, int out_size) {
    const float* x = (const float*)d_in[0];   // [16,1024,64]
    const float* y = (const float*)d_in[1];   // [16,4096,64]
    const float* xt = (const float*)d_in[2];  // [16,1024]
    const float* yt = (const float*)d_in[3];  // [16,4096]
    float* out = (float*)d_out;               // [16] cost, [16,1024] w_ts, [16,1024] w_vs

    int totalRows = BB * NN + BB * MM;
    norms_kernel<<<(totalRows + 255) / 256, 256>>>(x, y);

    init_bnd_kernel<<<(BB * NN + 255) / 256, 256>>>();

    dim3 gg(MM / 128, NN / 128, BB);
    gemm_kernel<<<gg, 256>>>(x, y);

    dtw_kernel<<<BB * 2, 256>>>();

    backtrack_kernel<<<BB, 32>>>(xt, yt, out);
}

// round 9
// speedup vs baseline: 2.9662x; 1.0210x over previous
#include <cuda_runtime.h>
#include <cuda_bf16.h>

// Problem constants: B=16, N=1024, M=4096, D=64
#define BB 16
#define NN 1024
#define MM 4096
#define DD 64
#define INF_BITS 0x7f800000u

// ---------------- device scratch (no cudaMalloc allowed) ----------------
__device__ float g_C[(size_t)BB * NN * MM];                 // 256 MB cost matrix
__device__ float g_x2[BB * NN];
__device__ float g_y2[BB * MM];
// packed moves: 4 cells per byte (2 bits each), row stride = MM/4 = 1024 bytes.
__device__ unsigned char g_mv[(size_t)BB * NN * (MM / 4) + 128];
// inter-CTA boundary handoff: 3 interfaces per batch, one word per row
__device__ unsigned g_bnd[BB][3][NN];
// per-CTA last-row argmin partials (4 CTAs per batch)
__device__ float g_pv[BB][4];
__device__ int g_pi[BB][4];

__device__ __forceinline__ unsigned ldcg_u32(const unsigned* p) {
    unsigned v;
    asm volatile("ld.global.cg.u32 %0, [%1];" : "=r"(v) : "l"(p));
    return v;
}
__device__ __forceinline__ void stcg_u32(unsigned* p, unsigned v) {
    asm volatile("st.global.cg.u32 [%0], %1;" :: "l"(p), "r"(v));
}

// ---------------- kernel 0a: row squared norms ----------------
__global__ void norms_kernel(const float* __restrict__ x, const float* __restrict__ y) {
    int idx = blockIdx.x * blockDim.x + threadIdx.x;
    const float* src;
    float* dst;
    if (idx < BB * NN) {
        src = x + (size_t)idx * DD;
        dst = g_x2 + idx;
    } else if (idx < BB * NN + BB * MM) {
        int k = idx - BB * NN;
        src = y + (size_t)k * DD;
        dst = g_y2 + k;
    } else {
        return;
    }
    float s = 0.f;
#pragma unroll
    for (int q = 0; q < DD / 4; q++) {
        float4 v = *(const float4*)(src + q * 4);
        s += v.x * v.x + v.y * v.y + v.z * v.z + v.w * v.w;
    }
    *dst = s;
}

// ---------------- kernel 0b: reset boundary sentinels ----------------
__global__ void init_bnd_kernel() {
    int i = blockIdx.x * blockDim.x + threadIdx.x;
    if (i < BB * 3 * NN) ((unsigned*)g_bnd)[i] = INF_BITS;
}

// ---------------- kernel 1: C = x2 + y2 - 2 * x @ y^T ----------------
__global__ void __launch_bounds__(256) gemm_kernel(const float* __restrict__ x,
                                                   const float* __restrict__ y) {
    __shared__ float Xs[32][128];
    __shared__ float Ys[32][128];
    int b = blockIdx.z;
    int i0 = blockIdx.y * 128;
    int j0 = blockIdx.x * 128;
    const float* xb = x + (size_t)b * NN * DD;
    const float* yb = y + (size_t)b * MM * DD;
    int tid = threadIdx.x;
    int txc = tid & 15, tyc = tid >> 4;

    float acc[8][8];
#pragma unroll
    for (int a = 0; a < 8; a++)
#pragma unroll
        for (int c = 0; c < 8; c++) acc[a][c] = 0.f;

#pragma unroll
    for (int kt = 0; kt < DD; kt += 32) {
#pragma unroll
        for (int p = 0; p < 4; p++) {
            int idx = tid + p * 256;
            int q = idx & 7;
            int r = idx >> 3;
            float4 xv = *(const float4*)(xb + (size_t)(i0 + r) * DD + kt + q * 4);
            Xs[q * 4 + 0][r] = xv.x;
            Xs[q * 4 + 1][r] = xv.y;
            Xs[q * 4 + 2][r] = xv.z;
            Xs[q * 4 + 3][r] = xv.w;
            float4 yv = *(const float4*)(yb + (size_t)(j0 + r) * DD + kt + q * 4);
            Ys[q * 4 + 0][r] = yv.x;
            Ys[q * 4 + 1][r] = yv.y;
            Ys[q * 4 + 2][r] = yv.z;
            Ys[q * 4 + 3][r] = yv.w;
        }
        __syncthreads();
#pragma unroll
        for (int kk = 0; kk < 32; kk++) {
            float xf[8], yf[8];
            *(float4*)&xf[0] = *(const float4*)&Xs[kk][tyc * 4];
            *(float4*)&xf[4] = *(const float4*)&Xs[kk][64 + tyc * 4];
            *(float4*)&yf[0] = *(const float4*)&Ys[kk][txc * 4];
            *(float4*)&yf[4] = *(const float4*)&Ys[kk][64 + txc * 4];
#pragma unroll
            for (int mm = 0; mm < 8; mm++)
#pragma unroll
                for (int nn = 0; nn < 8; nn++)
                    acc[mm][nn] = fmaf(xf[mm], yf[nn], acc[mm][nn]);
        }
        __syncthreads();
    }

    float y2v[8];
    *(float4*)&y2v[0] = *(const float4*)(g_y2 + b * MM + j0 + txc * 4);
    *(float4*)&y2v[4] = *(const float4*)(g_y2 + b * MM + j0 + 64 + txc * 4);
#pragma unroll
    for (int mm = 0; mm < 8; mm++) {
        int row = i0 + ((mm < 4) ? (tyc * 4 + mm) : (64 + tyc * 4 + mm - 4));
        float x2v = g_x2[b * NN + row];
        float* crow = g_C + ((size_t)b * NN + row) * MM + j0;
        float4 v0, v1;
        v0.x = x2v + y2v[0] - 2.f * acc[mm][0];
        v0.y = x2v + y2v[1] - 2.f * acc[mm][1];
        v0.z = x2v + y2v[2] - 2.f * acc[mm][2];
        v0.w = x2v + y2v[3] - 2.f * acc[mm][3];
        v1.x = x2v + y2v[4] - 2.f * acc[mm][4];
        v1.y = x2v + y2v[5] - 2.f * acc[mm][5];
        v1.z = x2v + y2v[6] - 2.f * acc[mm][6];
        v1.w = x2v + y2v[7] - 2.f * acc[mm][7];
        *(float4*)(crow + txc * 4) = v0;
        *(float4*)(crow + 64 + txc * 4) = v1;
    }
}

// ---------------- kernel 2: dataflow subsequence-DTW forward DP ----------------
// 4 CTAs per batch, 8 warps/CTA, warp owns 128 cols (4/lane, in regs).
// NO per-row barrier: each warp free-runs; the left boundary
// D[i][chunk_start-1] arrives through a value-as-flag smem word (INF
// sentinel, depth-128 SPSC ring, consumer clears, producer waits for a
// cleared slot before storing). Chunk ownership is REVERSED (warp 7 =
// leftmost chunk) so the dependency flows high-wid -> low-wid: spinning
// consumers always LOSE the hi-wid-first SMSP arbitration to their
// producers. Inter-CTA boundary: gmem word per row (unique slot), 2-deep
// prefetch.
// BUGFIX vs previous round: after the hoisted row-0 block the C-row
// prefetch pipeline (n1/n2/n3) is now ADVANCED, so iteration i reads C[i]
// (previously it re-read C[0] and skipped C[3], deterministically running
// the DP on a shifted cost matrix).
__global__ void __launch_bounds__(256, 1) dtw_kernel() {
    const unsigned FULL = 0xffffffffu;
    const float INF = __uint_as_float(INF_BITS);
    int cta = blockIdx.x;
    int b = cta >> 2, r = cta & 3;
    int t = threadIdx.x, lane = t & 31, w = t >> 5;
    int chunk = 7 - w;                          // 0 = leftmost chunk of this CTA
    int colbase = r * 1024 + chunk * 128 + lane * 4;
    const float* Cp = g_C + (size_t)b * NN * MM + colbase;
    unsigned char* mvp = g_mv + (size_t)b * NN * (MM / 4) + (colbase >> 2);

    __shared__ volatile unsigned sB[7][128];    // sB[w]: written by warp w+1, read by warp w
    __shared__ float sRv[8];
    __shared__ int sRi[8];
    for (int q = t; q < 7 * 128; q += 256) ((volatile unsigned*)sB)[q] = INF_BITS;
    __syncthreads();

    const bool gin = (w == 7 && r > 0);         // leftmost chunk consumes gmem boundary
    const bool gout = (w == 0 && r < 3);        // rightmost chunk produces gmem boundary
    const unsigned* gbi = gin ? &g_bnd[b][r - 1][0] : (const unsigned*)0;
    unsigned* gbo = gout ? &g_bnd[b][r][0] : (unsigned*)0;

    float n1[4], n2[4], n3[4];
    *(float4*)n1 = *(const float4*)(Cp);
    *(float4*)n2 = *(const float4*)(Cp + MM);
    *(float4*)n3 = *(const float4*)(Cp + 2 * (size_t)MM);

    // ---- row 0: D = C[0,:] ----
    float pd[4];
#pragma unroll
    for (int k = 0; k < 4; k++) pd[k] = n1[k];

    // acquire left boundary of row 0 (becomes prevB for row 1)
    float B = INF;
    unsigned pf1 = INF_BITS, pf2 = INF_BITS;
    if (w < 7) {
        unsigned vb;
        do { vb = sB[w][0]; } while (vb == INF_BITS);
        if (lane == 0) sB[w][0] = INF_BITS;
        B = __uint_as_float(vb);
    } else if (gin) {
        unsigned vb;
        do { vb = ldcg_u32(gbi + 0); } while (vb == INF_BITS);
        B = __uint_as_float(vb);
        pf1 = ldcg_u32(gbi + 1);
        pf2 = ldcg_u32(gbi + 2);
    }
    float prevB = B;

    // publish D[0][chunk_end] (slot 0 is guaranteed clear: init + barrier)
    {
        float dend = __shfl_sync(FULL, pd[3], 31);
        if (lane == 31) {
            unsigned ob = __float_as_uint(dend);
            if (w > 0) sB[w - 1][0] = ob;
            else if (gout) stcg_u32(gbo + 0, ob);
        }
    }

    // ---- ADVANCE the prefetch pipeline past row 0 (THE FIX) ----
#pragma unroll
    for (int k = 0; k < 4; k++) n1[k] = n2[k];      // n1 = C[1]
#pragma unroll
    for (int k = 0; k < 4; k++) n2[k] = n3[k];      // n2 = C[2]
    *(float4*)n3 = *(const float4*)(Cp + 3 * (size_t)MM);  // n3 = C[3]

    for (int i = 1; i < NN; i++) {
        float c[4];
#pragma unroll
        for (int k = 0; k < 4; k++) c[k] = n1[k];   // c = C[i]
#pragma unroll
        for (int k = 0; k < 4; k++) n1[k] = n2[k];
#pragma unroll
        for (int k = 0; k < 4; k++) n2[k] = n3[k];
        if (i + 3 < NN) *(float4*)n3 = *(const float4*)(Cp + (size_t)(i + 3) * MM);

        // pl = D[i-1][j-1]
        float pl0 = __shfl_up_sync(FULL, pd[3], 1);
        if (lane == 0) pl0 = prevB;
        float a[4];
        a[0] = fminf(pd[0], pl0) + c[0];
#pragma unroll
        for (int k = 1; k < 4; k++) a[k] = fminf(pd[k], pd[k - 1]) + c[k];

        // thread-local min-plus compose
        float Sl = c[0], Ml = a[0];
#pragma unroll
        for (int k = 1; k < 4; k++) {
            Sl += c[k];
            Ml = fminf(Ml + c[k], a[k]);
        }
        // warp inclusive min-plus pair scan (speculative w.r.t. boundary B)
        float iS = Sl, iM = Ml;
#pragma unroll
        for (int off = 1; off < 32; off <<= 1) {
            float oS = __shfl_up_sync(FULL, iS, off);
            float oM = __shfl_up_sync(FULL, iM, off);
            if (lane >= off) { iM = fminf(oM + iS, iM); iS = oS + iS; }
        }
        float eS = __shfl_up_sync(FULL, iS, 1);
        float eM = __shfl_up_sync(FULL, iM, 1);
        if (lane == 0) { eS = 0.f; eM = INF; }

        // acquire left boundary B = D[i][chunk_start-1]
        B = INF;
        if (w < 7) {
            unsigned vb;
            volatile unsigned* sl = &sB[w][i & 127];
            do { vb = *sl; } while (vb == INF_BITS);
            if (lane == 0) *sl = INF_BITS;
            B = __uint_as_float(vb);
        } else if (gin) {
            unsigned vb = pf1;
            while (vb == INF_BITS) vb = ldcg_u32(gbi + i);
            pf1 = pf2;
            int nx = (i + 2 < NN) ? (i + 2) : (NN - 1);
            pf2 = ldcg_u32(gbi + nx);
            B = __uint_as_float(vb);
        }

        // publish own boundary ASAP (lane 31 holds the chunk totals).
        // Back-pressure: wait for the consumer to have cleared the slot
        // before overwriting it (slot is reused every 128 rows).
        if (lane == 31) {
            float dend = fminf(B + iS, iM);
            unsigned ob = __float_as_uint(dend);
            if (w > 0) {
                volatile unsigned* so = &sB[w - 1][i & 127];
                while (*so != INF_BITS) {}
                *so = ob;
            } else if (gout) {
                stcg_u32(gbo + i, ob);
            }
        }

        // finalize with the carry applied
        float M_ex = fminf(B + eS, eM);         // == D[i][lane_start-1]
        float nd[4];
        float Mr = M_ex;
#pragma unroll
        for (int k = 0; k < 4; k++) {
            Mr = fminf(Mr + c[k], a[k]);
            nd[k] = Mr;
        }
        // move codes (dd = D[i-1][j-1], du = D[i-1][j], dl = D[i][j-1])
        unsigned pk = 0;
        float dl = M_ex, dd = pl0;
#pragma unroll
        for (int k = 0; k < 4; k++) {
            float du = pd[k];
            unsigned m = (du <= dl) ? 1u : 2u;
            if (dd <= du && dd <= dl) m = 0u;
            pk |= m << (2 * k);
            dd = du;
            dl = nd[k];
        }
        mvp[(size_t)i * (MM / 4)] = (unsigned char)pk;

        prevB = B;
#pragma unroll
        for (int k = 0; k < 4; k++) pd[k] = nd[k];
    }

    // ---- per-CTA argmin of last row (first index on exact ties) ----
    float bv = pd[0];
    int bi = colbase;
#pragma unroll
    for (int k = 1; k < 4; k++)
        if (pd[k] < bv) { bv = pd[k]; bi = colbase + k; }
#pragma unroll
    for (int off = 16; off > 0; off >>= 1) {
        float ov = __shfl_down_sync(FULL, bv, off);
        int oi = __shfl_down_sync(FULL, bi, off);
        if (ov < bv || (ov == bv && oi < bi)) { bv = ov; bi = oi; }
    }
    if (lane == 0) { sRv[w] = bv; sRi[w] = bi; }
    __syncthreads();
    if (t == 0) {
        float v = sRv[0]; int ix = sRi[0];
#pragma unroll
        for (int q = 1; q < 8; q++)
            if (sRv[q] < v || (sRv[q] == v && sRi[q] < ix)) { v = sRv[q]; ix = sRi[q]; }
        g_pv[b][r] = v;
        g_pi[b][r] = ix;
    }
}

// ---------------- kernel 3: backtrack over packed moves ----------------
// One warp per batch. 64-row x 20-word smem tile; lane0 walks it consuming a
// full 32-bit word (16 cells) at a time so left-runs cost ~1 LDS per 16 steps.
__global__ void __launch_bounds__(32) backtrack_kernel(const float* __restrict__ xt,
                                                       const float* __restrict__ yt,
                                                       float* __restrict__ out) {
    int b = blockIdx.x;
    int lane = threadIdx.x;
    __shared__ uint4 tile4[64][5];    // 64 rows x 80 bytes (20 words)
    __shared__ int syl[NN];
    __shared__ int sij[2];
    const unsigned* tw = (const unsigned*)tile4;
    const unsigned char* mvb = g_mv + (size_t)b * NN * (MM / 4);

    // final argmin across the 4 CTA partials (first global index on ties)
    if (lane == 0) {
        float bv = g_pv[b][0]; int bi = g_pi[b][0];
#pragma unroll
        for (int q = 1; q < 4; q++) {
            float v = g_pv[b][q]; int ix = g_pi[b][q];
            if (v < bv || (v == bv && ix < bi)) { bv = v; bi = ix; }
        }
        out[b] = bv;                  // dtw_cost
        syl[NN - 1] = bi;
        sij[0] = NN - 1; sij[1] = bi;
    }
    __syncwarp();
    int i = sij[0], j = sij[1];

    while (i > 0) {
        int r0 = i - 63; if (r0 < 1) r0 = 1;
        int wb0 = (j >> 4) - 15; if (wb0 < 0) wb0 = 0;
        wb0 &= ~3;                    // 16B-align the word window
#pragma unroll
        for (int p = 0; p < 10; p++) {
            int idx = lane + p * 32;  // 0..319
            int rr = idx / 5, q = idx - rr * 5;
            tile4[rr][q] = *(const uint4*)(mvb + (size_t)(r0 + rr) * (MM / 4) + wb0 * 4 + q * 16);
        }
        __syncwarp();
        if (lane == 0) {
            while (i > 0 && i >= r0) {
                int wcol = (j >> 4) - wb0;
                if (wcol < 0) break;
                unsigned word = tw[(i - r0) * 20 + wcol];
                for (;;) {
                    unsigned mv = (word >> ((j & 15) * 2)) & 3u;
                    if (mv == 2u) {           // left
                        j--;
                        if ((j & 15) == 15) break;   // crossed word boundary
                    } else {                  // diag or up
                        i--;
                        j -= (mv == 0u);
                        syl[i] = j;
                        break;
                    }
                }
            }
            sij[0] = i; sij[1] = j;
        }
        __syncwarp();
        i = sij[0]; j = sij[1];
        __syncwarp();
    }

    // write w_ts (= x_t) and w_vs (= y_t gathered at per-row path column)
    for (int n = lane; n < NN; n += 32) {
        out[BB + b * NN + n] = xt[b * NN + n];
        out[BB + BB * NN + b * NN + n] = yt[(size_t)b * MM + syl[n]];
    }
}

// ---------------- launch ----------------
extern "C" void kernel_launch(void* const* d_in, const int* in_sizes, int n_in,
                              void* d_out, int out_size) {
    const float* x = (const float*)d_in[0];   // [16,1024,64]
    const float* y = (const float*)d_in[1];   // [16,4096,64]
    const float* xt = (const float*)d_in[2];  // [16,1024]
    const float* yt = (const float*)d_in[3];  // [16,4096]
    float* out = (float*)d_out;               // [16] cost, [16,1024] w_ts, [16,1024] w_vs

    int totalRows = BB * NN + BB * MM;
    norms_kernel<<<(totalRows + 255) / 256, 256>>>(x, y);

    init_bnd_kernel<<<(BB * 3 * NN + 255) / 256, 256>>>();

    dim3 gg(MM / 128, NN / 128, BB);
    gemm_kernel<<<gg, 256>>>(x, y);

    dtw_kernel<<<BB * 4, 256>>>();

    backtrack_kernel<<<BB, 32>>>(xt, yt, out);
}

// round 11
// speedup vs baseline: 3.6150x; 1.2188x over previous
#include <cuda_runtime.h>
#include <cuda_bf16.h>

// Problem constants: B=16, N=1024, M=4096, D=64
#define BB 16
#define NN 1024
#define MM 4096
#define DD 64
#define INF_BITS 0x7f800000u

// ---------------- device scratch (no cudaMalloc allowed) ----------------
__device__ float g_C[(size_t)BB * NN * MM];                 // 256 MB cost matrix
__device__ float g_x2[BB * NN];
__device__ float g_y2[BB * MM];
// packed moves: 4 cells per byte (2 bits each), row stride = MM/4 = 1024 bytes.
__device__ unsigned char g_mv[(size_t)BB * NN * (MM / 4) + 128];
// inter-CTA boundary handoff: 3 interfaces per batch, one word per row
__device__ unsigned g_bnd[BB][3][NN];
// per-CTA last-row argmin partials (4 CTAs per batch)
__device__ float g_pv[BB][4];
__device__ int g_pi[BB][4];

__device__ __forceinline__ unsigned ldcg_u32(const unsigned* p) {
    unsigned v;
    asm volatile("ld.global.cg.u32 %0, [%1];" : "=r"(v) : "l"(p));
    return v;
}
__device__ __forceinline__ void stcg_u32(unsigned* p, unsigned v) {
    asm volatile("st.global.cg.u32 [%0], %1;" :: "l"(p), "r"(v));
}
__device__ __forceinline__ void cpasync16(void* smem_dst, const void* gsrc) {
    unsigned saddr;
    asm("{ .reg .u64 t; cvta.to.shared.u64 t, %1; cvt.u32.u64 %0, t; }"
        : "=r"(saddr) : "l"(smem_dst));
    asm volatile("cp.async.cg.shared.global [%0], [%1], 16;"
                 :: "r"(saddr), "l"(gsrc) : "memory");
}
#define CP_COMMIT() asm volatile("cp.async.commit_group;" ::: "memory")
#define CP_WAIT6()  asm volatile("cp.async.wait_group 6;" ::: "memory")

// ---------------- kernel 0a: row squared norms ----------------
__global__ void norms_kernel(const float* __restrict__ x, const float* __restrict__ y) {
    int idx = blockIdx.x * blockDim.x + threadIdx.x;
    const float* src;
    float* dst;
    if (idx < BB * NN) {
        src = x + (size_t)idx * DD;
        dst = g_x2 + idx;
    } else if (idx < BB * NN + BB * MM) {
        int k = idx - BB * NN;
        src = y + (size_t)k * DD;
        dst = g_y2 + k;
    } else {
        return;
    }
    float s = 0.f;
#pragma unroll
    for (int q = 0; q < DD / 4; q++) {
        float4 v = *(const float4*)(src + q * 4);
        s += v.x * v.x + v.y * v.y + v.z * v.z + v.w * v.w;
    }
    *dst = s;
}

// ---------------- kernel 0b: reset boundary sentinels ----------------
__global__ void init_bnd_kernel() {
    int i = blockIdx.x * blockDim.x + threadIdx.x;
    if (i < BB * 3 * NN) ((unsigned*)g_bnd)[i] = INF_BITS;
}

// ---------------- kernel 1: C = x2 + y2 - 2 * x @ y^T ----------------
__global__ void __launch_bounds__(256) gemm_kernel(const float* __restrict__ x,
                                                   const float* __restrict__ y) {
    __shared__ float Xs[32][128];
    __shared__ float Ys[32][128];
    int b = blockIdx.z;
    int i0 = blockIdx.y * 128;
    int j0 = blockIdx.x * 128;
    const float* xb = x + (size_t)b * NN * DD;
    const float* yb = y + (size_t)b * MM * DD;
    int tid = threadIdx.x;
    int txc = tid & 15, tyc = tid >> 4;

    float acc[8][8];
#pragma unroll
    for (int a = 0; a < 8; a++)
#pragma unroll
        for (int c = 0; c < 8; c++) acc[a][c] = 0.f;

#pragma unroll
    for (int kt = 0; kt < DD; kt += 32) {
#pragma unroll
        for (int p = 0; p < 4; p++) {
            int idx = tid + p * 256;
            int q = idx & 7;
            int r = idx >> 3;
            float4 xv = *(const float4*)(xb + (size_t)(i0 + r) * DD + kt + q * 4);
            Xs[q * 4 + 0][r] = xv.x;
            Xs[q * 4 + 1][r] = xv.y;
            Xs[q * 4 + 2][r] = xv.z;
            Xs[q * 4 + 3][r] = xv.w;
            float4 yv = *(const float4*)(yb + (size_t)(j0 + r) * DD + kt + q * 4);
            Ys[q * 4 + 0][r] = yv.x;
            Ys[q * 4 + 1][r] = yv.y;
            Ys[q * 4 + 2][r] = yv.z;
            Ys[q * 4 + 3][r] = yv.w;
        }
        __syncthreads();
#pragma unroll
        for (int kk = 0; kk < 32; kk++) {
            float xf[8], yf[8];
            *(float4*)&xf[0] = *(const float4*)&Xs[kk][tyc * 4];
            *(float4*)&xf[4] = *(const float4*)&Xs[kk][64 + tyc * 4];
            *(float4*)&yf[0] = *(const float4*)&Ys[kk][txc * 4];
            *(float4*)&yf[4] = *(const float4*)&Ys[kk][64 + txc * 4];
#pragma unroll
            for (int mm = 0; mm < 8; mm++)
#pragma unroll
                for (int nn = 0; nn < 8; nn++)
                    acc[mm][nn] = fmaf(xf[mm], yf[nn], acc[mm][nn]);
        }
        __syncthreads();
    }

    float y2v[8];
    *(float4*)&y2v[0] = *(const float4*)(g_y2 + b * MM + j0 + txc * 4);
    *(float4*)&y2v[4] = *(const float4*)(g_y2 + b * MM + j0 + 64 + txc * 4);
#pragma unroll
    for (int mm = 0; mm < 8; mm++) {
        int row = i0 + ((mm < 4) ? (tyc * 4 + mm) : (64 + tyc * 4 + mm - 4));
        float x2v = g_x2[b * NN + row];
        float* crow = g_C + ((size_t)b * NN + row) * MM + j0;
        float4 v0, v1;
        v0.x = x2v + y2v[0] - 2.f * acc[mm][0];
        v0.y = x2v + y2v[1] - 2.f * acc[mm][1];
        v0.z = x2v + y2v[2] - 2.f * acc[mm][2];
        v0.w = x2v + y2v[3] - 2.f * acc[mm][3];
        v1.x = x2v + y2v[4] - 2.f * acc[mm][4];
        v1.y = x2v + y2v[5] - 2.f * acc[mm][5];
        v1.z = x2v + y2v[6] - 2.f * acc[mm][6];
        v1.w = x2v + y2v[7] - 2.f * acc[mm][7];
        *(float4*)(crow + txc * 4) = v0;
        *(float4*)(crow + 64 + txc * 4) = v1;
    }
}

// ---------------- kernel 2: dataflow subsequence-DTW forward DP ----------------
// 4 CTAs per batch, 8 warps/CTA, warp owns 128 cols (4/lane, in regs).
// Free-running warps; left boundary via value-as-flag smem words (INF
// sentinel, depth-128 SPSC ring with producer back-pressure). Chunk
// ownership reversed (warp 7 = leftmost) so dependencies flow high-wid ->
// low-wid, aligning spins with the hi-wid-first arbiter.
// NEW vs previous round: C rows arrive through a cp.async smem ring with
// SIX rows genuinely in flight (the old n1/n2/n3 register pipeline had an
// effective depth of ONE because the register shift consumed the LDG next
// iteration, exposing ~600-900 cyc of DRAM latency every row). The
// inter-CTA gmem boundary is likewise loaded eagerly at row top so its L2
// latency overlaps the speculative scan.
__global__ void __launch_bounds__(256, 1) dtw_kernel() {
    const unsigned FULL = 0xffffffffu;
    const float INF = __uint_as_float(INF_BITS);
    int cta = blockIdx.x;
    int b = cta >> 2, r = cta & 3;
    int t = threadIdx.x, lane = t & 31, w = t >> 5;
    int chunk = 7 - w;                          // 0 = leftmost chunk of this CTA
    int colbase = r * 1024 + chunk * 128 + lane * 4;
    const float* Cp = g_C + (size_t)b * NN * MM + colbase;
    unsigned char* mvp = g_mv + (size_t)b * NN * (MM / 4) + (colbase >> 2);

    __shared__ volatile unsigned sB[7][128];    // sB[w]: written by warp w+1, read by warp w
    __shared__ float4 sring[8][8][32];          // per-warp 8-deep C-row ring (512B/row)
    __shared__ float sRv[8];
    __shared__ int sRi[8];
    for (int q = t; q < 7 * 128; q += 256) ((volatile unsigned*)sB)[q] = INF_BITS;
    __syncthreads();

    const bool gin = (w == 7 && r > 0);         // leftmost chunk consumes gmem boundary
    const bool gout = (w == 0 && r < 3);        // rightmost chunk produces gmem boundary
    const unsigned* gbi = gin ? &g_bnd[b][r - 1][0] : (const unsigned*)0;
    unsigned* gbo = gout ? &g_bnd[b][r][0] : (unsigned*)0;

    // ---- cp.async prologue: rows 0..5 in flight ----
#pragma unroll
    for (int k = 0; k < 6; k++) {
        cpasync16(&sring[w][k][lane], Cp + (size_t)k * MM);
        CP_COMMIT();
    }
    // issue row 6, then wait so row 0 is ready (groups pending <= 6)
    cpasync16(&sring[w][6][lane], Cp + 6 * (size_t)MM);
    CP_COMMIT();
    CP_WAIT6();

    // ---- row 0: D = C[0,:] ----
    float4 c4 = sring[w][0][lane];
    float pd[4] = {c4.x, c4.y, c4.z, c4.w};

    // acquire left boundary of row 0 (becomes prevB for row 1)
    float B = INF;
    if (w < 7) {
        unsigned vb;
        do { vb = sB[w][0]; } while (vb == INF_BITS);
        if (lane == 0) sB[w][0] = INF_BITS;
        B = __uint_as_float(vb);
    } else if (gin) {
        unsigned vb;
        do { vb = ldcg_u32(gbi + 0); } while (vb == INF_BITS);
        B = __uint_as_float(vb);
    }
    float prevB = B;

    // publish D[0][chunk_end] (slot 0 is guaranteed clear: init + barrier)
    {
        float dend = __shfl_sync(FULL, pd[3], 31);
        if (lane == 31) {
            unsigned ob = __float_as_uint(dend);
            if (w > 0) sB[w - 1][0] = ob;
            else if (gout) stcg_u32(gbo + 0, ob);
        }
    }

    for (int i = 1; i < NN; i++) {
        // keep 6 C rows in flight; ring slot (i+6)&7 reused from row i-2 (consumed)
        if (i + 6 < NN) cpasync16(&sring[w][(i + 6) & 7][lane], Cp + (size_t)(i + 6) * MM);
        CP_COMMIT();
        CP_WAIT6();                              // rows <= i ready

        // eager inter-CTA boundary load: latency overlaps the scan below
        unsigned vb0 = INF_BITS;
        if (gin && lane == 0) vb0 = ldcg_u32(gbi + i);

        float4 cc = sring[w][i & 7][lane];
        float c[4] = {cc.x, cc.y, cc.z, cc.w};

        // pl = D[i-1][j-1]
        float pl0 = __shfl_up_sync(FULL, pd[3], 1);
        if (lane == 0) pl0 = prevB;
        float a[4];
        a[0] = fminf(pd[0], pl0) + c[0];
#pragma unroll
        for (int k = 1; k < 4; k++) a[k] = fminf(pd[k], pd[k - 1]) + c[k];

        // thread-local min-plus compose
        float Sl = c[0], Ml = a[0];
#pragma unroll
        for (int k = 1; k < 4; k++) {
            Sl += c[k];
            Ml = fminf(Ml + c[k], a[k]);
        }
        // warp inclusive min-plus pair scan (speculative w.r.t. boundary B)
        float iS = Sl, iM = Ml;
#pragma unroll
        for (int off = 1; off < 32; off <<= 1) {
            float oS = __shfl_up_sync(FULL, iS, off);
            float oM = __shfl_up_sync(FULL, iM, off);
            if (lane >= off) { iM = fminf(oM + iS, iM); iS = oS + iS; }
        }
        float eS = __shfl_up_sync(FULL, iS, 1);
        float eM = __shfl_up_sync(FULL, iM, 1);
        if (lane == 0) { eS = 0.f; eM = INF; }

        // acquire left boundary B = D[i][chunk_start-1]
        B = INF;
        if (w < 7) {
            unsigned vb;
            volatile unsigned* sl = &sB[w][i & 127];
            do { vb = *sl; } while (vb == INF_BITS);
            if (lane == 0) *sl = INF_BITS;
            B = __uint_as_float(vb);
        } else if (gin) {
            if (lane == 0) {
                while (vb0 == INF_BITS) vb0 = ldcg_u32(gbi + i);
            }
            vb0 = __shfl_sync(FULL, vb0, 0);
            B = __uint_as_float(vb0);
        }

        // publish own boundary ASAP (lane 31 holds the chunk totals).
        // Back-pressure: wait for the consumer to have cleared the slot
        // before overwriting it (slot is reused every 128 rows).
        if (lane == 31) {
            float dend = fminf(B + iS, iM);
            unsigned ob = __float_as_uint(dend);
            if (w > 0) {
                volatile unsigned* so = &sB[w - 1][i & 127];
                while (*so != INF_BITS) {}
                *so = ob;
            } else if (gout) {
                stcg_u32(gbo + i, ob);
            }
        }

        // finalize with the carry applied
        float M_ex = fminf(B + eS, eM);         // == D[i][lane_start-1]
        float nd[4];
        float Mr = M_ex;
#pragma unroll
        for (int k = 0; k < 4; k++) {
            Mr = fminf(Mr + c[k], a[k]);
            nd[k] = Mr;
        }
        // move codes (dd = D[i-1][j-1], du = D[i-1][j], dl = D[i][j-1])
        unsigned pk = 0;
        float dl = M_ex, dd = pl0;
#pragma unroll
        for (int k = 0; k < 4; k++) {
            float du = pd[k];
            unsigned m = (du <= dl) ? 1u : 2u;
            if (dd <= du && dd <= dl) m = 0u;
            pk |= m << (2 * k);
            dd = du;
            dl = nd[k];
        }
        mvp[(size_t)i * (MM / 4)] = (unsigned char)pk;

        prevB = B;
#pragma unroll
        for (int k = 0; k < 4; k++) pd[k] = nd[k];
    }

    // ---- per-CTA argmin of last row (first index on exact ties) ----
    float bv = pd[0];
    int bi = colbase;
#pragma unroll
    for (int k = 1; k < 4; k++)
        if (pd[k] < bv) { bv = pd[k]; bi = colbase + k; }
#pragma unroll
    for (int off = 16; off > 0; off >>= 1) {
        float ov = __shfl_down_sync(FULL, bv, off);
        int oi = __shfl_down_sync(FULL, bi, off);
        if (ov < bv || (ov == bv && oi < bi)) { bv = ov; bi = oi; }
    }
    if (lane == 0) { sRv[w] = bv; sRi[w] = bi; }
    __syncthreads();
    if (t == 0) {
        float v = sRv[0]; int ix = sRi[0];
#pragma unroll
        for (int q = 1; q < 8; q++)
            if (sRv[q] < v || (sRv[q] == v && sRi[q] < ix)) { v = sRv[q]; ix = sRi[q]; }
        g_pv[b][r] = v;
        g_pi[b][r] = ix;
    }
}

// ---------------- kernel 3: backtrack over packed moves ----------------
// One warp per batch. 64-row x 20-word smem tile; lane0 walks it consuming a
// full 32-bit word (16 cells) at a time so left-runs cost ~1 LDS per 16 steps.
__global__ void __launch_bounds__(32) backtrack_kernel(const float* __restrict__ xt,
                                                       const float* __restrict__ yt,
                                                       float* __restrict__ out) {
    int b = blockIdx.x;
    int lane = threadIdx.x;
    __shared__ uint4 tile4[64][5];    // 64 rows x 80 bytes (20 words)
    __shared__ int syl[NN];
    __shared__ int sij[2];
    const unsigned* tw = (const unsigned*)tile4;
    const unsigned char* mvb = g_mv + (size_t)b * NN * (MM / 4);

    // final argmin across the 4 CTA partials (first global index on ties)
    if (lane == 0) {
        float bv = g_pv[b][0]; int bi = g_pi[b][0];
#pragma unroll
        for (int q = 1; q < 4; q++) {
            float v = g_pv[b][q]; int ix = g_pi[b][q];
            if (v < bv || (v == bv && ix < bi)) { bv = v; bi = ix; }
        }
        out[b] = bv;                  // dtw_cost
        syl[NN - 1] = bi;
        sij[0] = NN - 1; sij[1] = bi;
    }
    __syncwarp();
    int i = sij[0], j = sij[1];

    while (i > 0) {
        int r0 = i - 63; if (r0 < 1) r0 = 1;
        int wb0 = (j >> 4) - 15; if (wb0 < 0) wb0 = 0;
        wb0 &= ~3;                    // 16B-align the word window
#pragma unroll
        for (int p = 0; p < 10; p++) {
            int idx = lane + p * 32;  // 0..319
            int rr = idx / 5, q = idx - rr * 5;
            tile4[rr][q] = *(const uint4*)(mvb + (size_t)(r0 + rr) * (MM / 4) + wb0 * 4 + q * 16);
        }
        __syncwarp();
        if (lane == 0) {
            while (i > 0 && i >= r0) {
                int wcol = (j >> 4) - wb0;
                if (wcol < 0) break;
                unsigned word = tw[(i - r0) * 20 + wcol];
                for (;;) {
                    unsigned mv = (word >> ((j & 15) * 2)) & 3u;
                    if (mv == 2u) {           // left
                        j--;
                        if ((j & 15) == 15) break;   // crossed word boundary
                    } else {                  // diag or up
                        i--;
                        j -= (mv == 0u);
                        syl[i] = j;
                        break;
                    }
                }
            }
            sij[0] = i; sij[1] = j;
        }
        __syncwarp();
        i = sij[0]; j = sij[1];
        __syncwarp();
    }

    // write w_ts (= x_t) and w_vs (= y_t gathered at per-row path column)
    for (int n = lane; n < NN; n += 32) {
        out[BB + b * NN + n] = xt[b * NN + n];
        out[BB + BB * NN + b * NN + n] = yt[(size_t)b * MM + syl[n]];
    }
}

// ---------------- launch ----------------
extern "C" void kernel_launch(void* const* d_in, const int* in_sizes, int n_in,
                              void* d_out, int out_size) {
    const float* x = (const float*)d_in[0];   // [16,1024,64]
    const float* y = (const float*)d_in[1];   // [16,4096,64]
    const float* xt = (const float*)d_in[2];  // [16,1024]
    const float* yt = (const float*)d_in[3];  // [16,4096]
    float* out = (float*)d_out;               // [16] cost, [16,1024] w_ts, [16,1024] w_vs

    int totalRows = BB * NN + BB * MM;
    norms_kernel<<<(totalRows + 255) / 256, 256>>>(x, y);

    init_bnd_kernel<<<(BB * 3 * NN + 255) / 256, 256>>>();

    dim3 gg(MM / 128, NN / 128, BB);
    gemm_kernel<<<gg, 256>>>(x, y);

    dtw_kernel<<<BB * 4, 256>>>();

    backtrack_kernel<<<BB, 32>>>(xt, yt, out);
}